// round 15
// baseline (speedup 1.0000x reference)
#include <cuda_runtime.h>
#include <cuda_fp16.h>
#include <stdint.h>

// N=100000 nodes, F=128 feat, R=4 relations, E=1600000 edges, L=2 layers.
#define NN 100000
#define FF 128
#define RR 4
#define EE 1600000
#define NB (NN * RR)                 // (dst,relation) bins, bin = r*NN + dst
#define NBLK ((NB + 1023) / 1024)    // 391 scan blocks
#define NSEG 5                       // 4 relations + root per layer
#define NTILE ((NN + 127) / 128)     // 782 row tiles
#define PERSIST_BLOCKS 296           // 148 SMs x 2 resident blocks

// Device-global scratch (no cudaMalloc allowed). fp16 activations/means/weights.
__device__ uint2 g_xh[(size_t)NN * 32];          // x as fp16 [N][128]
__device__ uint2 g_xh2[(size_t)NN * 32];         // layer-0 output as fp16
__device__ uint2 g_aggh[(size_t)RR * NN * 32];   // per-bin mean as fp16
__device__ __half g_wh[(size_t)2 * NSEG * FF * FF];  // [layer*5+seg][n][k] fp16
__device__ int g_hist[NB];
__device__ int g_offs[NB];
__device__ int g_cursor[NB];
__device__ int g_perm[EE];                       // src indices sorted by bin
__device__ int g_bsum[NBLK];
__device__ int g_bsumx[NBLK];
__device__ int g_scan_done;                      // single-pass scan ticket
__device__ int g_scan_flag;                      // single-pass scan release flag

__device__ __forceinline__ uint32_t h2_to_u32(__half2 h) {
    return *reinterpret_cast<uint32_t*>(&h);
}
__device__ __forceinline__ __half2 u32_to_h2(uint32_t u) {
    return *reinterpret_cast<__half2*>(&u);
}

// ---------------------------------------------------------------------------
// One-time prep: x->fp16, weights->fp16 transposed, hist zero, scan-state zero.
// ---------------------------------------------------------------------------
__global__ void prep_kernel(const float* __restrict__ x,
                            const float* __restrict__ weights,
                            const float* __restrict__ roots) {
    const size_t stride = (size_t)gridDim.x * blockDim.x;
    const size_t tid0 = (size_t)blockIdx.x * blockDim.x + threadIdx.x;

    if (tid0 == 0) { g_scan_done = 0; g_scan_flag = 0; }

    const float4* in = reinterpret_cast<const float4*>(x);
    for (size_t i = tid0; i < (size_t)NN * 32; i += stride) {
        float4 v = in[i];
        uint2 o;
        o.x = h2_to_u32(__floats2half2_rn(v.x, v.y));
        o.y = h2_to_u32(__floats2half2_rn(v.z, v.w));
        g_xh[i] = o;
    }
    for (size_t i = tid0; i < (size_t)2 * NSEG * FF * FF; i += stride) {
        int si = (int)(i >> 14);
        int rem = (int)(i & 16383);
        int n = rem >> 7;
        int k = rem & 127;
        int l = si / NSEG;
        int seg = si % NSEG;
        const float* src = (seg < RR)
            ? weights + ((size_t)(l * RR + seg)) * FF * FF
            : roots + (size_t)l * FF * FF;
        g_wh[i] = __float2half_rn(src[k * FF + n]);
    }
    for (size_t i = tid0; i < (size_t)NB; i += stride)
        g_hist[i] = 0;
}

// ---------------------------------------------------------------------------
// Counting sort of edges by (relation, dst).
// ---------------------------------------------------------------------------
__global__ void hist_build_kernel(const int* __restrict__ ei,
                                  const int* __restrict__ et) {
    int e = blockIdx.x * blockDim.x + threadIdx.x;
    if (e >= EE) return;
    int dst = __ldg(&ei[EE + e]);
    int r = __ldg(&et[e]);
    atomicAdd(&g_hist[r * NN + dst], 1);
}

// Single-pass scan: per-block local scan; last-done block scans the block
// sums; all blocks (co-resident: 391 blocks) spin on a flag, then write
// final offsets + cursors from registers.
__global__ void scan_kernel() {
    __shared__ int sh[256];
    __shared__ int sh_bcast;
    int t = threadIdx.x;
    int base = blockIdx.x * 1024 + t * 4;

    int v0 = (base + 0 < NB) ? g_hist[base + 0] : 0;
    int v1 = (base + 1 < NB) ? g_hist[base + 1] : 0;
    int v2 = (base + 2 < NB) ? g_hist[base + 2] : 0;
    int v3 = (base + 3 < NB) ? g_hist[base + 3] : 0;
    int s = v0 + v1 + v2 + v3;
    sh[t] = s;
    __syncthreads();
    for (int off = 1; off < 256; off <<= 1) {
        int add = (t >= off) ? sh[t - off] : 0;
        __syncthreads();
        sh[t] += add;
        __syncthreads();
    }
    int e0 = sh[t] - s;
    int e1 = e0 + v0;
    int e2 = e1 + v1;
    int e3 = e2 + v2;
    if (t == 255) g_bsum[blockIdx.x] = sh[255];
    __threadfence();

    __shared__ int isLast;
    if (t == 0) isLast = (atomicAdd(&g_scan_done, 1) == gridDim.x - 1) ? 1 : 0;
    __syncthreads();

    if (isLast) {
        int a0 = (2 * t     < NBLK) ? __ldcg(&g_bsum[2 * t])     : 0;
        int a1 = (2 * t + 1 < NBLK) ? __ldcg(&g_bsum[2 * t + 1]) : 0;
        int ss = a0 + a1;
        __syncthreads();
        sh[t] = ss;
        __syncthreads();
        for (int off = 1; off < 256; off <<= 1) {
            int add = (t >= off) ? sh[t - off] : 0;
            __syncthreads();
            sh[t] += add;
            __syncthreads();
        }
        int ex = sh[t] - ss;
        if (2 * t     < NBLK) g_bsumx[2 * t]     = ex;
        if (2 * t + 1 < NBLK) g_bsumx[2 * t + 1] = ex + a0;
        __threadfence();
        __syncthreads();
        if (t == 0) atomicExch(&g_scan_flag, 1);
    }

    if (t == 0) {
        while (atomicAdd(&g_scan_flag, 0) == 0) { }
        sh_bcast = atomicAdd(&g_bsumx[blockIdx.x], 0);
    }
    __syncthreads();
    int add = sh_bcast;

    if (base + 0 < NB) { int o = e0 + add; g_offs[base + 0] = o; g_cursor[base + 0] = o; }
    if (base + 1 < NB) { int o = e1 + add; g_offs[base + 1] = o; g_cursor[base + 1] = o; }
    if (base + 2 < NB) { int o = e2 + add; g_offs[base + 2] = o; g_cursor[base + 2] = o; }
    if (base + 3 < NB) { int o = e3 + add; g_offs[base + 3] = o; g_cursor[base + 3] = o; }
}

__global__ void place_kernel(const int* __restrict__ ei,
                             const int* __restrict__ et) {
    int e = blockIdx.x * blockDim.x + threadIdx.x;
    if (e >= EE) return;
    int src = __ldg(&ei[e]);
    int dst = __ldg(&ei[EE + e]);
    int r = __ldg(&et[e]);
    int pos = atomicAdd(&g_cursor[r * NN + dst], 1);
    g_perm[pos] = src;
}

// ---------------------------------------------------------------------------
// Segmented mean aggregation (R8-identical, FROZEN): one warp per bin,
// broadcast perm loads, unroll-2 gathers, fp32 accumulate, fp16 mean.
// ---------------------------------------------------------------------------
__global__ void aggregate_kernel(int xsel) {
    const uint2* __restrict__ xp = xsel ? g_xh2 : g_xh;
    int w = (int)(((size_t)blockIdx.x * blockDim.x + threadIdx.x) >> 5);
    int lane = threadIdx.x & 31;
    if (w >= NB) return;

    int start = __ldg(&g_offs[w]);
    int cnt = __ldg(&g_hist[w]);

    float2 a0 = make_float2(0.f, 0.f), a1 = make_float2(0.f, 0.f);
    float2 b0 = make_float2(0.f, 0.f), b1 = make_float2(0.f, 0.f);
    int i = 0;
    for (; i + 1 < cnt; i += 2) {
        int s0 = __ldg(&g_perm[start + i]);
        int s1 = __ldg(&g_perm[start + i + 1]);
        uint2 v0 = __ldg(xp + (size_t)s0 * 32 + lane);
        uint2 v1 = __ldg(xp + (size_t)s1 * 32 + lane);
        float2 f;
        f = __half22float2(u32_to_h2(v0.x)); a0.x += f.x; a0.y += f.y;
        f = __half22float2(u32_to_h2(v0.y)); a1.x += f.x; a1.y += f.y;
        f = __half22float2(u32_to_h2(v1.x)); b0.x += f.x; b0.y += f.y;
        f = __half22float2(u32_to_h2(v1.y)); b1.x += f.x; b1.y += f.y;
    }
    if (i < cnt) {
        int s0 = __ldg(&g_perm[start + i]);
        uint2 v0 = __ldg(xp + (size_t)s0 * 32 + lane);
        float2 f;
        f = __half22float2(u32_to_h2(v0.x)); a0.x += f.x; a0.y += f.y;
        f = __half22float2(u32_to_h2(v0.y)); a1.x += f.x; a1.y += f.y;
    }
    float inv = (cnt > 0) ? 1.0f / (float)cnt : 0.f;
    uint2 o;
    o.x = h2_to_u32(__floats2half2_rn((a0.x + b0.x) * inv, (a0.y + b0.y) * inv));
    o.y = h2_to_u32(__floats2half2_rn((a1.x + b1.x) * inv, (a1.y + b1.y) * inv));
    g_aggh[(size_t)w * 32 + lane] = o;
}

// ---------------------------------------------------------------------------
// PERSISTENT fp16 tensor GEMM: out = relu(sum_r mean_r@W_r + x@root + b).
// Virtual [N,640]x[640,128] fp16 mma m16n8k16, fp32 accumulate.
// BM=128, BN=128, BK=32 -> 20 chunks, 3-stage cp.async pipeline.
// Grid = 296 persistent blocks (148 SMs x 2 resident); each block loops over
// row tiles, eliminating the 2.64-wave quantization of the 782-block launch.
// Per-tile body identical to R14.
// ---------------------------------------------------------------------------
#define T_STRIDE 20                       // u32 per row
#define T_BUF (128 * T_STRIDE)            // u32 per tile buffer
#define GEMM_SMEM (3 * 2 * T_BUF * 4)     // 61440 B

__device__ __forceinline__ void issue_chunk(int ct, int stage, int row0,
                                            const uint2* __restrict__ xroot,
                                            int wbase, uint32_t sA, uint32_t sB) {
    const int tid = threadIdx.x;
    const int seg = ct >> 2;                   // 0..4
    const int kloc = (ct & 3) << 5;            // 0,32,64,96 (halves)
    const __half* Abase = (seg < RR)
        ? reinterpret_cast<const __half*>(g_aggh) + ((size_t)seg * NN) * FF
        : reinterpret_cast<const __half*>(xroot);
    const __half* Bbase = g_wh + (size_t)(wbase + seg) * FF * FF;

#pragma unroll
    for (int t = 0; t < 2; ++t) {
        int idx = tid + t * 256;
        int r = idx >> 2;
        int g16 = idx & 3;
        int gr = row0 + r;
        const __half* src = Abase + (size_t)gr * FF + kloc + g16 * 8;
        uint32_t dst = sA + (stage * 2 * T_BUF + r * T_STRIDE + g16 * 4) * 4;
        int p = (gr < NN) ? 16 : 0;
        asm volatile("cp.async.cg.shared.global [%0], [%1], 16, %2;\n"
                     :: "r"(dst), "l"(src), "r"(p));
    }
#pragma unroll
    for (int t = 0; t < 2; ++t) {
        int idx = tid + t * 256;
        int n = idx >> 2;
        int g16 = idx & 3;
        const __half* src = Bbase + (size_t)n * FF + kloc + g16 * 8;
        uint32_t dst = sB + (stage * 2 * T_BUF + n * T_STRIDE + g16 * 4) * 4;
        asm volatile("cp.async.cg.shared.global [%0], [%1], 16;\n"
                     :: "r"(dst), "l"(src));
    }
}

__global__ __launch_bounds__(256, 2)
void gemm_kernel(int xroot_sel,                 // 0 -> g_xh, 1 -> g_xh2
                 int wbase,                     // 0 (layer0) or NSEG (layer1)
                 const float* __restrict__ bias,
                 float* __restrict__ out_f32,   // non-null: final fp32 output
                 int out_h_sel) {               // else: 1 -> write fp16 g_xh2
    const uint2* __restrict__ xroot = xroot_sel ? g_xh2 : g_xh;

    extern __shared__ uint32_t smem[];
    uint32_t* As = smem;
    uint32_t* Bs = smem + T_BUF;
    uint32_t sA = (uint32_t)__cvta_generic_to_shared(As);
    uint32_t sB = (uint32_t)__cvta_generic_to_shared(Bs);

    const int tid = threadIdx.x;
    const int lane = tid & 31;
    const int wid = tid >> 5;
    const int warp_m = wid & 1;
    const int warp_n = wid >> 1;
    const int q = lane >> 2;
    const int c = lane & 3;

    for (int tile = blockIdx.x; tile < NTILE; tile += gridDim.x) {
        const int row0 = tile * 128;

        float acc[4][4][4];
#pragma unroll
        for (int mi = 0; mi < 4; ++mi)
#pragma unroll
            for (int ni = 0; ni < 4; ++ni)
#pragma unroll
                for (int j = 0; j < 4; ++j) acc[mi][ni][j] = 0.f;

        issue_chunk(0, 0, row0, xroot, wbase, sA, sB);
        asm volatile("cp.async.commit_group;\n" ::: "memory");
        issue_chunk(1, 1, row0, xroot, wbase, sA, sB);
        asm volatile("cp.async.commit_group;\n" ::: "memory");

        for (int ct = 0; ct < 20; ++ct) {
            if (ct + 2 < 20) {
                issue_chunk(ct + 2, (ct + 2) % 3, row0, xroot, wbase, sA, sB);
                asm volatile("cp.async.commit_group;\n" ::: "memory");
                asm volatile("cp.async.wait_group 2;\n" ::: "memory");
            } else if (ct + 1 < 20) {
                asm volatile("cp.async.wait_group 1;\n" ::: "memory");
            } else {
                asm volatile("cp.async.wait_group 0;\n" ::: "memory");
            }
            __syncthreads();

            const int stage = ct % 3;
            const uint32_t* Ab = As + stage * 2 * T_BUF;
            const uint32_t* Bb = Bs + stage * 2 * T_BUF;
#pragma unroll
            for (int ks = 0; ks < 2; ++ks) {
                const int ko = ks * 8;
                uint32_t a[4][4];
#pragma unroll
                for (int mi = 0; mi < 4; ++mi) {
                    int row = warp_m * 64 + mi * 16 + q;
                    a[mi][0] = Ab[row * T_STRIDE + ko + c];
                    a[mi][1] = Ab[(row + 8) * T_STRIDE + ko + c];
                    a[mi][2] = Ab[row * T_STRIDE + ko + c + 4];
                    a[mi][3] = Ab[(row + 8) * T_STRIDE + ko + c + 4];
                }
                uint32_t b[4][2];
#pragma unroll
                for (int ni = 0; ni < 4; ++ni) {
                    int col = warp_n * 32 + ni * 8 + q;
                    b[ni][0] = Bb[col * T_STRIDE + ko + c];
                    b[ni][1] = Bb[col * T_STRIDE + ko + c + 4];
                }
#pragma unroll
                for (int mi = 0; mi < 4; ++mi)
#pragma unroll
                    for (int ni = 0; ni < 4; ++ni) {
                        asm volatile(
                            "mma.sync.aligned.m16n8k16.row.col.f32.f16.f16.f32 "
                            "{%0,%1,%2,%3}, {%4,%5,%6,%7}, {%8,%9}, {%0,%1,%2,%3};\n"
                            : "+f"(acc[mi][ni][0]), "+f"(acc[mi][ni][1]),
                              "+f"(acc[mi][ni][2]), "+f"(acc[mi][ni][3])
                            : "r"(a[mi][0]), "r"(a[mi][1]), "r"(a[mi][2]), "r"(a[mi][3]),
                              "r"(b[ni][0]), "r"(b[ni][1]));
                    }
            }
            __syncthreads();
        }

        // Epilogue: bias + relu. fp32 (final) or fp16 (inter-layer).
        // No smem access here, so the next tile's prologue can't race it.
#pragma unroll
        for (int ni = 0; ni < 4; ++ni) {
            int col = warp_n * 32 + ni * 8 + c * 2;
            float b0 = __ldg(&bias[col]);
            float b1 = __ldg(&bias[col + 1]);
#pragma unroll
            for (int mi = 0; mi < 4; ++mi) {
                int gr0 = row0 + warp_m * 64 + mi * 16 + q;
                int gr1 = gr0 + 8;
                float v00 = fmaxf(acc[mi][ni][0] + b0, 0.f);
                float v01 = fmaxf(acc[mi][ni][1] + b1, 0.f);
                float v10 = fmaxf(acc[mi][ni][2] + b0, 0.f);
                float v11 = fmaxf(acc[mi][ni][3] + b1, 0.f);
                if (out_f32) {
                    if (gr0 < NN)
                        *reinterpret_cast<float2*>(out_f32 + (size_t)gr0 * FF + col)
                            = make_float2(v00, v01);
                    if (gr1 < NN)
                        *reinterpret_cast<float2*>(out_f32 + (size_t)gr1 * FF + col)
                            = make_float2(v10, v11);
                } else if (out_h_sel) {
                    uint32_t* oh = reinterpret_cast<uint32_t*>(g_xh2);
                    if (gr0 < NN)
                        oh[(size_t)gr0 * 64 + (col >> 1)] =
                            h2_to_u32(__floats2half2_rn(v00, v01));
                    if (gr1 < NN)
                        oh[(size_t)gr1 * 64 + (col >> 1)] =
                            h2_to_u32(__floats2half2_rn(v10, v11));
                }
            }
        }
    }
}

// ---------------------------------------------------------------------------
extern "C" void kernel_launch(void* const* d_in, const int* in_sizes, int n_in,
                              void* d_out, int out_size) {
    const float* x       = (const float*)d_in[0];   // [N, F] f32
    const int*   ei      = (const int*)d_in[1];     // [2, E] int32
    const int*   et      = (const int*)d_in[2];     // [E]    int32
    const float* weights = (const float*)d_in[3];   // [L, R, F, F]
    const float* roots   = (const float*)d_in[4];   // [L, F, F]
    const float* biases  = (const float*)d_in[5];   // [L, F]
    float* out           = (float*)d_out;           // [N, F]

    const int edge_blocks = (EE + 255) / 256;       // 6250
    const int agg_blocks  = (NB * 32 + 255) / 256;  // 50000 (warp per bin)

    cudaFuncSetAttribute(gemm_kernel,
                         cudaFuncAttributeMaxDynamicSharedMemorySize, GEMM_SMEM);

    // One-time prep + counting sort of edges by (relation, dst).
    prep_kernel<<<1024, 256>>>(x, weights, roots);
    hist_build_kernel<<<edge_blocks, 256>>>(ei, et);
    scan_kernel<<<NBLK, 256>>>();
    place_kernel<<<edge_blocks, 256>>>(ei, et);

    // Layer 0: g_xh -> g_xh2 (fp16)
    aggregate_kernel<<<agg_blocks, 256>>>(0);
    gemm_kernel<<<PERSIST_BLOCKS, 256, GEMM_SMEM>>>(0, 0, biases, nullptr, 1);

    // Layer 1: g_xh2 -> out (fp32)
    aggregate_kernel<<<agg_blocks, 256>>>(1);
    gemm_kernel<<<PERSIST_BLOCKS, 256, GEMM_SMEM>>>(1, NSEG, biases + FF, out, 0);
}

// round 16
// speedup vs baseline: 1.0168x; 1.0168x over previous
#include <cuda_runtime.h>
#include <cuda_fp16.h>
#include <stdint.h>

// N=100000 nodes, F=128 feat, R=4 relations, E=1600000 edges, L=2 layers.
#define NN 100000
#define FF 128
#define RR 4
#define EE 1600000
#define NB (NN * RR)                 // (dst,relation) bins, bin = r*NN + dst
#define NBLK ((NB + 1023) / 1024)    // 391 scan blocks
#define NSEG 5                       // 4 relations + root per layer

// Device-global scratch (no cudaMalloc allowed). fp16 activations/means/weights.
__device__ uint2 g_xh[(size_t)NN * 32];          // x as fp16 [N][128]
__device__ uint2 g_xh2[(size_t)NN * 32];         // layer-0 output as fp16
__device__ uint2 g_aggh[(size_t)RR * NN * 32];   // per-bin mean as fp16
__device__ __half g_wh[(size_t)2 * NSEG * FF * FF];  // [layer*5+seg][n][k] fp16
__device__ int g_hist[NB];
__device__ int g_offs[NB];
__device__ int g_cursor[NB];
__device__ int g_perm[EE];                       // src indices sorted by bin
__device__ int g_bsum[NBLK];
__device__ int g_bsumx[NBLK];
__device__ int g_scan_done;                      // single-pass scan ticket
__device__ int g_scan_flag;                      // single-pass scan release flag

// Side stream + fork/join events, created once at static init (host-side
// driver resources only — no tracked device memory).
static cudaStream_t g_s2;
static cudaEvent_t g_ev_fork, g_ev_join;
static struct StreamInit {
    StreamInit() {
        cudaStreamCreateWithFlags(&g_s2, cudaStreamNonBlocking);
        cudaEventCreateWithFlags(&g_ev_fork, cudaEventDisableTiming);
        cudaEventCreateWithFlags(&g_ev_join, cudaEventDisableTiming);
    }
} g_stream_init;

__device__ __forceinline__ uint32_t h2_to_u32(__half2 h) {
    return *reinterpret_cast<uint32_t*>(&h);
}
__device__ __forceinline__ __half2 u32_to_h2(uint32_t u) {
    return *reinterpret_cast<__half2*>(&u);
}

// ---------------------------------------------------------------------------
// Zero hist + scan state (main stream, ahead of hist_build).
// ---------------------------------------------------------------------------
__global__ void zero_kernel() {
    const size_t stride = (size_t)gridDim.x * blockDim.x;
    const size_t tid0 = (size_t)blockIdx.x * blockDim.x + threadIdx.x;
    if (tid0 == 0) { g_scan_done = 0; g_scan_flag = 0; }
    for (size_t i = tid0; i < (size_t)NB; i += stride)
        g_hist[i] = 0;
}

// ---------------------------------------------------------------------------
// fp16 conversions (side stream — overlaps the sort chain).
// ---------------------------------------------------------------------------
__global__ void convert_kernel(const float* __restrict__ x,
                               const float* __restrict__ weights,
                               const float* __restrict__ roots) {
    const size_t stride = (size_t)gridDim.x * blockDim.x;
    const size_t tid0 = (size_t)blockIdx.x * blockDim.x + threadIdx.x;

    const float4* in = reinterpret_cast<const float4*>(x);
    for (size_t i = tid0; i < (size_t)NN * 32; i += stride) {
        float4 v = in[i];
        uint2 o;
        o.x = h2_to_u32(__floats2half2_rn(v.x, v.y));
        o.y = h2_to_u32(__floats2half2_rn(v.z, v.w));
        g_xh[i] = o;
    }
    for (size_t i = tid0; i < (size_t)2 * NSEG * FF * FF; i += stride) {
        int si = (int)(i >> 14);
        int rem = (int)(i & 16383);
        int n = rem >> 7;
        int k = rem & 127;
        int l = si / NSEG;
        int seg = si % NSEG;
        const float* src = (seg < RR)
            ? weights + ((size_t)(l * RR + seg)) * FF * FF
            : roots + (size_t)l * FF * FF;
        g_wh[i] = __float2half_rn(src[k * FF + n]);
    }
}

// ---------------------------------------------------------------------------
// Counting sort of edges by (relation, dst).
// ---------------------------------------------------------------------------
__global__ void hist_build_kernel(const int* __restrict__ ei,
                                  const int* __restrict__ et) {
    int e = blockIdx.x * blockDim.x + threadIdx.x;
    if (e >= EE) return;
    int dst = __ldg(&ei[EE + e]);
    int r = __ldg(&et[e]);
    atomicAdd(&g_hist[r * NN + dst], 1);
}

// Single-pass scan: per-block local scan; last-done block scans the block
// sums; all blocks (co-resident: 391 blocks) spin on a flag, then write
// final offsets + cursors from registers.
__global__ void scan_kernel() {
    __shared__ int sh[256];
    __shared__ int sh_bcast;
    int t = threadIdx.x;
    int base = blockIdx.x * 1024 + t * 4;

    int v0 = (base + 0 < NB) ? g_hist[base + 0] : 0;
    int v1 = (base + 1 < NB) ? g_hist[base + 1] : 0;
    int v2 = (base + 2 < NB) ? g_hist[base + 2] : 0;
    int v3 = (base + 3 < NB) ? g_hist[base + 3] : 0;
    int s = v0 + v1 + v2 + v3;
    sh[t] = s;
    __syncthreads();
    for (int off = 1; off < 256; off <<= 1) {
        int add = (t >= off) ? sh[t - off] : 0;
        __syncthreads();
        sh[t] += add;
        __syncthreads();
    }
    int e0 = sh[t] - s;
    int e1 = e0 + v0;
    int e2 = e1 + v1;
    int e3 = e2 + v2;
    if (t == 255) g_bsum[blockIdx.x] = sh[255];
    __threadfence();

    __shared__ int isLast;
    if (t == 0) isLast = (atomicAdd(&g_scan_done, 1) == gridDim.x - 1) ? 1 : 0;
    __syncthreads();

    if (isLast) {
        int a0 = (2 * t     < NBLK) ? __ldcg(&g_bsum[2 * t])     : 0;
        int a1 = (2 * t + 1 < NBLK) ? __ldcg(&g_bsum[2 * t + 1]) : 0;
        int ss = a0 + a1;
        __syncthreads();
        sh[t] = ss;
        __syncthreads();
        for (int off = 1; off < 256; off <<= 1) {
            int add = (t >= off) ? sh[t - off] : 0;
            __syncthreads();
            sh[t] += add;
            __syncthreads();
        }
        int ex = sh[t] - ss;
        if (2 * t     < NBLK) g_bsumx[2 * t]     = ex;
        if (2 * t + 1 < NBLK) g_bsumx[2 * t + 1] = ex + a0;
        __threadfence();
        __syncthreads();
        if (t == 0) atomicExch(&g_scan_flag, 1);
    }

    if (t == 0) {
        while (atomicAdd(&g_scan_flag, 0) == 0) { }
        sh_bcast = atomicAdd(&g_bsumx[blockIdx.x], 0);
    }
    __syncthreads();
    int add = sh_bcast;

    if (base + 0 < NB) { int o = e0 + add; g_offs[base + 0] = o; g_cursor[base + 0] = o; }
    if (base + 1 < NB) { int o = e1 + add; g_offs[base + 1] = o; g_cursor[base + 1] = o; }
    if (base + 2 < NB) { int o = e2 + add; g_offs[base + 2] = o; g_cursor[base + 2] = o; }
    if (base + 3 < NB) { int o = e3 + add; g_offs[base + 3] = o; g_cursor[base + 3] = o; }
}

__global__ void place_kernel(const int* __restrict__ ei,
                             const int* __restrict__ et) {
    int e = blockIdx.x * blockDim.x + threadIdx.x;
    if (e >= EE) return;
    int src = __ldg(&ei[e]);
    int dst = __ldg(&ei[EE + e]);
    int r = __ldg(&et[e]);
    int pos = atomicAdd(&g_cursor[r * NN + dst], 1);
    g_perm[pos] = src;
}

// ---------------------------------------------------------------------------
// Segmented mean aggregation (R8-identical, FROZEN): one warp per bin,
// broadcast perm loads, unroll-2 gathers, fp32 accumulate, fp16 mean.
// ---------------------------------------------------------------------------
__global__ void aggregate_kernel(int xsel) {
    const uint2* __restrict__ xp = xsel ? g_xh2 : g_xh;
    int w = (int)(((size_t)blockIdx.x * blockDim.x + threadIdx.x) >> 5);
    int lane = threadIdx.x & 31;
    if (w >= NB) return;

    int start = __ldg(&g_offs[w]);
    int cnt = __ldg(&g_hist[w]);

    float2 a0 = make_float2(0.f, 0.f), a1 = make_float2(0.f, 0.f);
    float2 b0 = make_float2(0.f, 0.f), b1 = make_float2(0.f, 0.f);
    int i = 0;
    for (; i + 1 < cnt; i += 2) {
        int s0 = __ldg(&g_perm[start + i]);
        int s1 = __ldg(&g_perm[start + i + 1]);
        uint2 v0 = __ldg(xp + (size_t)s0 * 32 + lane);
        uint2 v1 = __ldg(xp + (size_t)s1 * 32 + lane);
        float2 f;
        f = __half22float2(u32_to_h2(v0.x)); a0.x += f.x; a0.y += f.y;
        f = __half22float2(u32_to_h2(v0.y)); a1.x += f.x; a1.y += f.y;
        f = __half22float2(u32_to_h2(v1.x)); b0.x += f.x; b0.y += f.y;
        f = __half22float2(u32_to_h2(v1.y)); b1.x += f.x; b1.y += f.y;
    }
    if (i < cnt) {
        int s0 = __ldg(&g_perm[start + i]);
        uint2 v0 = __ldg(xp + (size_t)s0 * 32 + lane);
        float2 f;
        f = __half22float2(u32_to_h2(v0.x)); a0.x += f.x; a0.y += f.y;
        f = __half22float2(u32_to_h2(v0.y)); a1.x += f.x; a1.y += f.y;
    }
    float inv = (cnt > 0) ? 1.0f / (float)cnt : 0.f;
    uint2 o;
    o.x = h2_to_u32(__floats2half2_rn((a0.x + b0.x) * inv, (a0.y + b0.y) * inv));
    o.y = h2_to_u32(__floats2half2_rn((a1.x + b1.x) * inv, (a1.y + b1.y) * inv));
    g_aggh[(size_t)w * 32 + lane] = o;
}

// ---------------------------------------------------------------------------
// fp16 tensor GEMM (R14-identical, 782-block launch): out = relu(...).
// Virtual [N,640]x[640,128] fp16 mma m16n8k16, fp32 accumulate.
// BM=128, BN=128, BK=32 -> 20 chunks, 3-stage cp.async pipeline.
// ---------------------------------------------------------------------------
#define T_STRIDE 20                       // u32 per row
#define T_BUF (128 * T_STRIDE)            // u32 per tile buffer
#define GEMM_SMEM (3 * 2 * T_BUF * 4)     // 61440 B

__device__ __forceinline__ void issue_chunk(int ct, int stage, int row0,
                                            const uint2* __restrict__ xroot,
                                            int wbase, uint32_t sA, uint32_t sB) {
    const int tid = threadIdx.x;
    const int seg = ct >> 2;                   // 0..4
    const int kloc = (ct & 3) << 5;            // 0,32,64,96 (halves)
    const __half* Abase = (seg < RR)
        ? reinterpret_cast<const __half*>(g_aggh) + ((size_t)seg * NN) * FF
        : reinterpret_cast<const __half*>(xroot);
    const __half* Bbase = g_wh + (size_t)(wbase + seg) * FF * FF;

#pragma unroll
    for (int t = 0; t < 2; ++t) {
        int idx = tid + t * 256;
        int r = idx >> 2;
        int g16 = idx & 3;
        int gr = row0 + r;
        const __half* src = Abase + (size_t)gr * FF + kloc + g16 * 8;
        uint32_t dst = sA + (stage * 2 * T_BUF + r * T_STRIDE + g16 * 4) * 4;
        int p = (gr < NN) ? 16 : 0;
        asm volatile("cp.async.cg.shared.global [%0], [%1], 16, %2;\n"
                     :: "r"(dst), "l"(src), "r"(p));
    }
#pragma unroll
    for (int t = 0; t < 2; ++t) {
        int idx = tid + t * 256;
        int n = idx >> 2;
        int g16 = idx & 3;
        const __half* src = Bbase + (size_t)n * FF + kloc + g16 * 8;
        uint32_t dst = sB + (stage * 2 * T_BUF + n * T_STRIDE + g16 * 4) * 4;
        asm volatile("cp.async.cg.shared.global [%0], [%1], 16;\n"
                     :: "r"(dst), "l"(src));
    }
}

__global__ __launch_bounds__(256, 2)
void gemm_kernel(int xroot_sel,                 // 0 -> g_xh, 1 -> g_xh2
                 int wbase,                     // 0 (layer0) or NSEG (layer1)
                 const float* __restrict__ bias,
                 float* __restrict__ out_f32,   // non-null: final fp32 output
                 int out_h_sel) {               // else: 1 -> write fp16 g_xh2
    const uint2* __restrict__ xroot = xroot_sel ? g_xh2 : g_xh;

    extern __shared__ uint32_t smem[];
    uint32_t* As = smem;
    uint32_t* Bs = smem + T_BUF;
    uint32_t sA = (uint32_t)__cvta_generic_to_shared(As);
    uint32_t sB = (uint32_t)__cvta_generic_to_shared(Bs);

    const int tid = threadIdx.x;
    const int lane = tid & 31;
    const int wid = tid >> 5;
    const int warp_m = wid & 1;
    const int warp_n = wid >> 1;
    const int q = lane >> 2;
    const int c = lane & 3;
    const int row0 = blockIdx.x * 128;

    float acc[4][4][4];
#pragma unroll
    for (int mi = 0; mi < 4; ++mi)
#pragma unroll
        for (int ni = 0; ni < 4; ++ni)
#pragma unroll
            for (int j = 0; j < 4; ++j) acc[mi][ni][j] = 0.f;

    issue_chunk(0, 0, row0, xroot, wbase, sA, sB);
    asm volatile("cp.async.commit_group;\n" ::: "memory");
    issue_chunk(1, 1, row0, xroot, wbase, sA, sB);
    asm volatile("cp.async.commit_group;\n" ::: "memory");

    for (int ct = 0; ct < 20; ++ct) {
        if (ct + 2 < 20) {
            issue_chunk(ct + 2, (ct + 2) % 3, row0, xroot, wbase, sA, sB);
            asm volatile("cp.async.commit_group;\n" ::: "memory");
            asm volatile("cp.async.wait_group 2;\n" ::: "memory");
        } else if (ct + 1 < 20) {
            asm volatile("cp.async.wait_group 1;\n" ::: "memory");
        } else {
            asm volatile("cp.async.wait_group 0;\n" ::: "memory");
        }
        __syncthreads();

        const int stage = ct % 3;
        const uint32_t* Ab = As + stage * 2 * T_BUF;
        const uint32_t* Bb = Bs + stage * 2 * T_BUF;
#pragma unroll
        for (int ks = 0; ks < 2; ++ks) {
            const int ko = ks * 8;
            uint32_t a[4][4];
#pragma unroll
            for (int mi = 0; mi < 4; ++mi) {
                int row = warp_m * 64 + mi * 16 + q;
                a[mi][0] = Ab[row * T_STRIDE + ko + c];
                a[mi][1] = Ab[(row + 8) * T_STRIDE + ko + c];
                a[mi][2] = Ab[row * T_STRIDE + ko + c + 4];
                a[mi][3] = Ab[(row + 8) * T_STRIDE + ko + c + 4];
            }
            uint32_t b[4][2];
#pragma unroll
            for (int ni = 0; ni < 4; ++ni) {
                int col = warp_n * 32 + ni * 8 + q;
                b[ni][0] = Bb[col * T_STRIDE + ko + c];
                b[ni][1] = Bb[col * T_STRIDE + ko + c + 4];
            }
#pragma unroll
            for (int mi = 0; mi < 4; ++mi)
#pragma unroll
                for (int ni = 0; ni < 4; ++ni) {
                    asm volatile(
                        "mma.sync.aligned.m16n8k16.row.col.f32.f16.f16.f32 "
                        "{%0,%1,%2,%3}, {%4,%5,%6,%7}, {%8,%9}, {%0,%1,%2,%3};\n"
                        : "+f"(acc[mi][ni][0]), "+f"(acc[mi][ni][1]),
                          "+f"(acc[mi][ni][2]), "+f"(acc[mi][ni][3])
                        : "r"(a[mi][0]), "r"(a[mi][1]), "r"(a[mi][2]), "r"(a[mi][3]),
                          "r"(b[ni][0]), "r"(b[ni][1]));
                }
        }
        __syncthreads();
    }

    // Epilogue: bias + relu. fp32 (final) or fp16 (inter-layer).
#pragma unroll
    for (int ni = 0; ni < 4; ++ni) {
        int col = warp_n * 32 + ni * 8 + c * 2;
        float b0 = __ldg(&bias[col]);
        float b1 = __ldg(&bias[col + 1]);
#pragma unroll
        for (int mi = 0; mi < 4; ++mi) {
            int gr0 = row0 + warp_m * 64 + mi * 16 + q;
            int gr1 = gr0 + 8;
            float v00 = fmaxf(acc[mi][ni][0] + b0, 0.f);
            float v01 = fmaxf(acc[mi][ni][1] + b1, 0.f);
            float v10 = fmaxf(acc[mi][ni][2] + b0, 0.f);
            float v11 = fmaxf(acc[mi][ni][3] + b1, 0.f);
            if (out_f32) {
                if (gr0 < NN)
                    *reinterpret_cast<float2*>(out_f32 + (size_t)gr0 * FF + col)
                        = make_float2(v00, v01);
                if (gr1 < NN)
                    *reinterpret_cast<float2*>(out_f32 + (size_t)gr1 * FF + col)
                        = make_float2(v10, v11);
            } else if (out_h_sel) {
                uint32_t* oh = reinterpret_cast<uint32_t*>(g_xh2);
                if (gr0 < NN)
                    oh[(size_t)gr0 * 64 + (col >> 1)] =
                        h2_to_u32(__floats2half2_rn(v00, v01));
                if (gr1 < NN)
                    oh[(size_t)gr1 * 64 + (col >> 1)] =
                        h2_to_u32(__floats2half2_rn(v10, v11));
            }
        }
    }
}

// ---------------------------------------------------------------------------
extern "C" void kernel_launch(void* const* d_in, const int* in_sizes, int n_in,
                              void* d_out, int out_size) {
    const float* x       = (const float*)d_in[0];   // [N, F] f32
    const int*   ei      = (const int*)d_in[1];     // [2, E] int32
    const int*   et      = (const int*)d_in[2];     // [E]    int32
    const float* weights = (const float*)d_in[3];   // [L, R, F, F]
    const float* roots   = (const float*)d_in[4];   // [L, F, F]
    const float* biases  = (const float*)d_in[5];   // [L, F]
    float* out           = (float*)d_out;           // [N, F]

    const int edge_blocks = (EE + 255) / 256;       // 6250
    const int agg_blocks  = (NB * 32 + 255) / 256;  // 50000 (warp per bin)
    const int gemm_blocks = (NN + 127) / 128;       // 782

    cudaFuncSetAttribute(gemm_kernel,
                         cudaFuncAttributeMaxDynamicSharedMemorySize, GEMM_SMEM);

    // Fork: fp16 conversions on side stream overlap the sort chain.
    cudaEventRecord(g_ev_fork, 0);
    cudaStreamWaitEvent(g_s2, g_ev_fork, 0);
    convert_kernel<<<1024, 256, 0, g_s2>>>(x, weights, roots);

    // Main stream: counting sort of edges by (relation, dst).
    zero_kernel<<<512, 256>>>();
    hist_build_kernel<<<edge_blocks, 256>>>(ei, et);
    scan_kernel<<<NBLK, 256>>>();
    place_kernel<<<edge_blocks, 256>>>(ei, et);

    // Join: aggregate needs both g_xh (side) and perm (main).
    cudaEventRecord(g_ev_join, g_s2);
    cudaStreamWaitEvent(0, g_ev_join, 0);

    // Layer 0: g_xh -> g_xh2 (fp16)
    aggregate_kernel<<<agg_blocks, 256>>>(0);
    gemm_kernel<<<gemm_blocks, 256, GEMM_SMEM>>>(0, 0, biases, nullptr, 1);

    // Layer 1: g_xh2 -> out (fp32)
    aggregate_kernel<<<agg_blocks, 256>>>(1);
    gemm_kernel<<<gemm_blocks, 256, GEMM_SMEM>>>(1, NSEG, biases + FF, out, 0);
}

// round 17
// speedup vs baseline: 1.0186x; 1.0018x over previous
#include <cuda_runtime.h>
#include <cuda_fp16.h>
#include <stdint.h>

// N=100000 nodes, F=128 feat, R=4 relations, E=1600000 edges, L=2 layers.
#define NN 100000
#define FF 128
#define RR 4
#define EE 1600000
#define NB (NN * RR)                 // (dst,relation) bins, bin = r*NN + dst
#define NBLK ((NB + 1023) / 1024)    // 391 scan blocks
#define NSEG 5                       // 4 relations + root per layer

// Device-global scratch (no cudaMalloc allowed). fp16 activations/means/weights.
// NOTE: g_hist relies on (a) zero-initialization of __device__ globals for the
// first execution and (b) re-zeroing inside the layer-1 GEMM for every
// subsequent graph replay. Scan ticket/flag are reset in place_kernel.
__device__ uint2 g_xh[(size_t)NN * 32];          // x as fp16 [N][128]
__device__ uint2 g_xh2[(size_t)NN * 32];         // layer-0 output as fp16
__device__ uint2 g_aggh[(size_t)RR * NN * 32];   // per-bin mean as fp16
__device__ __half g_wh[(size_t)2 * NSEG * FF * FF];  // [layer*5+seg][n][k] fp16
__device__ int g_hist[NB];
__device__ int g_offs[NB];
__device__ int g_cursor[NB];
__device__ int g_perm[EE];                       // src indices sorted by bin
__device__ int g_bsum[NBLK];
__device__ int g_bsumx[NBLK];
__device__ int g_scan_done;                      // single-pass scan ticket
__device__ int g_scan_flag;                      // single-pass scan release flag

__device__ __forceinline__ uint32_t h2_to_u32(__half2 h) {
    return *reinterpret_cast<uint32_t*>(&h);
}
__device__ __forceinline__ __half2 u32_to_h2(uint32_t u) {
    return *reinterpret_cast<__half2*>(&u);
}

// ---------------------------------------------------------------------------
// Counting sort of edges by (relation, dst). g_hist is zero at entry
// (zero-init on first call; re-zeroed by layer-1 GEMM on every execution).
// ---------------------------------------------------------------------------
__global__ void hist_build_kernel(const int* __restrict__ ei,
                                  const int* __restrict__ et) {
    int e = blockIdx.x * blockDim.x + threadIdx.x;
    if (e >= EE) return;
    int dst = __ldg(&ei[EE + e]);
    int r = __ldg(&et[e]);
    atomicAdd(&g_hist[r * NN + dst], 1);
}

// Single-pass scan: per-block local scan; last-done block scans the block
// sums; all blocks (co-resident: 391 blocks) spin on a flag, then write
// final offsets + cursors from registers. g_scan_done/g_scan_flag are zero
// at entry (zero-init first call; reset by place_kernel afterwards).
__global__ void scan_kernel() {
    __shared__ int sh[256];
    __shared__ int sh_bcast;
    int t = threadIdx.x;
    int base = blockIdx.x * 1024 + t * 4;

    int v0 = (base + 0 < NB) ? g_hist[base + 0] : 0;
    int v1 = (base + 1 < NB) ? g_hist[base + 1] : 0;
    int v2 = (base + 2 < NB) ? g_hist[base + 2] : 0;
    int v3 = (base + 3 < NB) ? g_hist[base + 3] : 0;
    int s = v0 + v1 + v2 + v3;
    sh[t] = s;
    __syncthreads();
    for (int off = 1; off < 256; off <<= 1) {
        int add = (t >= off) ? sh[t - off] : 0;
        __syncthreads();
        sh[t] += add;
        __syncthreads();
    }
    int e0 = sh[t] - s;
    int e1 = e0 + v0;
    int e2 = e1 + v1;
    int e3 = e2 + v2;
    if (t == 255) g_bsum[blockIdx.x] = sh[255];
    __threadfence();

    __shared__ int isLast;
    if (t == 0) isLast = (atomicAdd(&g_scan_done, 1) == gridDim.x - 1) ? 1 : 0;
    __syncthreads();

    if (isLast) {
        int a0 = (2 * t     < NBLK) ? __ldcg(&g_bsum[2 * t])     : 0;
        int a1 = (2 * t + 1 < NBLK) ? __ldcg(&g_bsum[2 * t + 1]) : 0;
        int ss = a0 + a1;
        __syncthreads();
        sh[t] = ss;
        __syncthreads();
        for (int off = 1; off < 256; off <<= 1) {
            int add = (t >= off) ? sh[t - off] : 0;
            __syncthreads();
            sh[t] += add;
            __syncthreads();
        }
        int ex = sh[t] - ss;
        if (2 * t     < NBLK) g_bsumx[2 * t]     = ex;
        if (2 * t + 1 < NBLK) g_bsumx[2 * t + 1] = ex + a0;
        __threadfence();
        __syncthreads();
        if (t == 0) atomicExch(&g_scan_flag, 1);
    }

    if (t == 0) {
        while (atomicAdd(&g_scan_flag, 0) == 0) { }
        sh_bcast = atomicAdd(&g_bsumx[blockIdx.x], 0);
    }
    __syncthreads();
    int add = sh_bcast;

    if (base + 0 < NB) { int o = e0 + add; g_offs[base + 0] = o; g_cursor[base + 0] = o; }
    if (base + 1 < NB) { int o = e1 + add; g_offs[base + 1] = o; g_cursor[base + 1] = o; }
    if (base + 2 < NB) { int o = e2 + add; g_offs[base + 2] = o; g_cursor[base + 2] = o; }
    if (base + 3 < NB) { int o = e3 + add; g_offs[base + 3] = o; g_cursor[base + 3] = o; }
}

// ---------------------------------------------------------------------------
// Placement + fp16 conversions fused. Place is latency-bound (issue ~5%), so
// the bandwidth-bound convert work fills its idle issue slots. Also resets
// the scan ticket/flag for the next execution (scan fully done by stream
// order before this kernel starts).
// ---------------------------------------------------------------------------
__global__ void place_conv_kernel(const int* __restrict__ ei,
                                  const int* __restrict__ et,
                                  const float* __restrict__ x,
                                  const float* __restrict__ weights,
                                  const float* __restrict__ roots) {
    const int tid0 = blockIdx.x * blockDim.x + threadIdx.x;
    const size_t stride = (size_t)gridDim.x * blockDim.x;   // EE threads total

    if (tid0 == 0) { g_scan_done = 0; g_scan_flag = 0; }

    // Place: one edge per thread (measured best).
    if (tid0 < EE) {
        int src = __ldg(&ei[tid0]);
        int dst = __ldg(&ei[EE + tid0]);
        int r = __ldg(&et[tid0]);
        int pos = atomicAdd(&g_cursor[r * NN + dst], 1);
        g_perm[pos] = src;
    }

    // Convert x -> fp16 (3.2M quads over 1.6M threads = 2 iters).
    const float4* in = reinterpret_cast<const float4*>(x);
    for (size_t i = tid0; i < (size_t)NN * 32; i += stride) {
        float4 v = in[i];
        uint2 o;
        o.x = h2_to_u32(__floats2half2_rn(v.x, v.y));
        o.y = h2_to_u32(__floats2half2_rn(v.z, v.w));
        g_xh[i] = o;
    }
    // Convert weights+roots -> fp16 transposed [l*5+seg][n][k].
    for (size_t i = tid0; i < (size_t)2 * NSEG * FF * FF; i += stride) {
        int si = (int)(i >> 14);
        int rem = (int)(i & 16383);
        int n = rem >> 7;
        int k = rem & 127;
        int l = si / NSEG;
        int seg = si % NSEG;
        const float* src = (seg < RR)
            ? weights + ((size_t)(l * RR + seg)) * FF * FF
            : roots + (size_t)l * FF * FF;
        g_wh[i] = __float2half_rn(src[k * FF + n]);
    }
}

// ---------------------------------------------------------------------------
// Segmented mean aggregation (R8-identical, FROZEN): one warp per bin,
// broadcast perm loads, unroll-2 gathers, fp32 accumulate, fp16 mean.
// ---------------------------------------------------------------------------
__global__ void aggregate_kernel(int xsel) {
    const uint2* __restrict__ xp = xsel ? g_xh2 : g_xh;
    int w = (int)(((size_t)blockIdx.x * blockDim.x + threadIdx.x) >> 5);
    int lane = threadIdx.x & 31;
    if (w >= NB) return;

    int start = __ldg(&g_offs[w]);
    int cnt = __ldg(&g_hist[w]);

    float2 a0 = make_float2(0.f, 0.f), a1 = make_float2(0.f, 0.f);
    float2 b0 = make_float2(0.f, 0.f), b1 = make_float2(0.f, 0.f);
    int i = 0;
    for (; i + 1 < cnt; i += 2) {
        int s0 = __ldg(&g_perm[start + i]);
        int s1 = __ldg(&g_perm[start + i + 1]);
        uint2 v0 = __ldg(xp + (size_t)s0 * 32 + lane);
        uint2 v1 = __ldg(xp + (size_t)s1 * 32 + lane);
        float2 f;
        f = __half22float2(u32_to_h2(v0.x)); a0.x += f.x; a0.y += f.y;
        f = __half22float2(u32_to_h2(v0.y)); a1.x += f.x; a1.y += f.y;
        f = __half22float2(u32_to_h2(v1.x)); b0.x += f.x; b0.y += f.y;
        f = __half22float2(u32_to_h2(v1.y)); b1.x += f.x; b1.y += f.y;
    }
    if (i < cnt) {
        int s0 = __ldg(&g_perm[start + i]);
        uint2 v0 = __ldg(xp + (size_t)s0 * 32 + lane);
        float2 f;
        f = __half22float2(u32_to_h2(v0.x)); a0.x += f.x; a0.y += f.y;
        f = __half22float2(u32_to_h2(v0.y)); a1.x += f.x; a1.y += f.y;
    }
    float inv = (cnt > 0) ? 1.0f / (float)cnt : 0.f;
    uint2 o;
    o.x = h2_to_u32(__floats2half2_rn((a0.x + b0.x) * inv, (a0.y + b0.y) * inv));
    o.y = h2_to_u32(__floats2half2_rn((a1.x + b1.x) * inv, (a1.y + b1.y) * inv));
    g_aggh[(size_t)w * 32 + lane] = o;
}

// ---------------------------------------------------------------------------
// fp16 tensor GEMM (R14-identical body): out = relu(sum_r mean_r@W_r + x@root + b).
// Virtual [N,640]x[640,128] fp16 mma m16n8k16, fp32 accumulate.
// BM=128, BN=128, BK=32 -> 20 chunks, 3-stage cp.async pipeline.
// Layer-1 call (out_f32 != null) also re-zeros g_hist for the next execution
// (hist is dead after agg1; the zeroing hides under the GEMM).
// ---------------------------------------------------------------------------
#define T_STRIDE 20                       // u32 per row
#define T_BUF (128 * T_STRIDE)            // u32 per tile buffer
#define GEMM_SMEM (3 * 2 * T_BUF * 4)     // 61440 B

__device__ __forceinline__ void issue_chunk(int ct, int stage, int row0,
                                            const uint2* __restrict__ xroot,
                                            int wbase, uint32_t sA, uint32_t sB) {
    const int tid = threadIdx.x;
    const int seg = ct >> 2;                   // 0..4
    const int kloc = (ct & 3) << 5;            // 0,32,64,96 (halves)
    const __half* Abase = (seg < RR)
        ? reinterpret_cast<const __half*>(g_aggh) + ((size_t)seg * NN) * FF
        : reinterpret_cast<const __half*>(xroot);
    const __half* Bbase = g_wh + (size_t)(wbase + seg) * FF * FF;

#pragma unroll
    for (int t = 0; t < 2; ++t) {
        int idx = tid + t * 256;
        int r = idx >> 2;
        int g16 = idx & 3;
        int gr = row0 + r;
        const __half* src = Abase + (size_t)gr * FF + kloc + g16 * 8;
        uint32_t dst = sA + (stage * 2 * T_BUF + r * T_STRIDE + g16 * 4) * 4;
        int p = (gr < NN) ? 16 : 0;
        asm volatile("cp.async.cg.shared.global [%0], [%1], 16, %2;\n"
                     :: "r"(dst), "l"(src), "r"(p));
    }
#pragma unroll
    for (int t = 0; t < 2; ++t) {
        int idx = tid + t * 256;
        int n = idx >> 2;
        int g16 = idx & 3;
        const __half* src = Bbase + (size_t)n * FF + kloc + g16 * 8;
        uint32_t dst = sB + (stage * 2 * T_BUF + n * T_STRIDE + g16 * 4) * 4;
        asm volatile("cp.async.cg.shared.global [%0], [%1], 16;\n"
                     :: "r"(dst), "l"(src));
    }
}

__global__ __launch_bounds__(256, 2)
void gemm_kernel(int xroot_sel,                 // 0 -> g_xh, 1 -> g_xh2
                 int wbase,                     // 0 (layer0) or NSEG (layer1)
                 const float* __restrict__ bias,
                 float* __restrict__ out_f32,   // non-null: final fp32 output
                 int out_h_sel) {               // else: 1 -> write fp16 g_xh2
    const uint2* __restrict__ xroot = xroot_sel ? g_xh2 : g_xh;

    extern __shared__ uint32_t smem[];
    uint32_t* As = smem;
    uint32_t* Bs = smem + T_BUF;
    uint32_t sA = (uint32_t)__cvta_generic_to_shared(As);
    uint32_t sB = (uint32_t)__cvta_generic_to_shared(Bs);

    const int tid = threadIdx.x;

    // Layer-1 only: re-zero g_hist for the next graph replay (hist is dead
    // after agg1, which completed before this launch by stream order).
    if (out_f32) {
        const size_t gstride = (size_t)gridDim.x * blockDim.x;
        for (size_t i = (size_t)blockIdx.x * blockDim.x + tid; i < (size_t)NB;
             i += gstride)
            g_hist[i] = 0;
    }

    const int lane = tid & 31;
    const int wid = tid >> 5;
    const int warp_m = wid & 1;
    const int warp_n = wid >> 1;
    const int q = lane >> 2;
    const int c = lane & 3;
    const int row0 = blockIdx.x * 128;

    float acc[4][4][4];
#pragma unroll
    for (int mi = 0; mi < 4; ++mi)
#pragma unroll
        for (int ni = 0; ni < 4; ++ni)
#pragma unroll
            for (int j = 0; j < 4; ++j) acc[mi][ni][j] = 0.f;

    issue_chunk(0, 0, row0, xroot, wbase, sA, sB);
    asm volatile("cp.async.commit_group;\n" ::: "memory");
    issue_chunk(1, 1, row0, xroot, wbase, sA, sB);
    asm volatile("cp.async.commit_group;\n" ::: "memory");

    for (int ct = 0; ct < 20; ++ct) {
        if (ct + 2 < 20) {
            issue_chunk(ct + 2, (ct + 2) % 3, row0, xroot, wbase, sA, sB);
            asm volatile("cp.async.commit_group;\n" ::: "memory");
            asm volatile("cp.async.wait_group 2;\n" ::: "memory");
        } else if (ct + 1 < 20) {
            asm volatile("cp.async.wait_group 1;\n" ::: "memory");
        } else {
            asm volatile("cp.async.wait_group 0;\n" ::: "memory");
        }
        __syncthreads();

        const int stage = ct % 3;
        const uint32_t* Ab = As + stage * 2 * T_BUF;
        const uint32_t* Bb = Bs + stage * 2 * T_BUF;
#pragma unroll
        for (int ks = 0; ks < 2; ++ks) {
            const int ko = ks * 8;
            uint32_t a[4][4];
#pragma unroll
            for (int mi = 0; mi < 4; ++mi) {
                int row = warp_m * 64 + mi * 16 + q;
                a[mi][0] = Ab[row * T_STRIDE + ko + c];
                a[mi][1] = Ab[(row + 8) * T_STRIDE + ko + c];
                a[mi][2] = Ab[row * T_STRIDE + ko + c + 4];
                a[mi][3] = Ab[(row + 8) * T_STRIDE + ko + c + 4];
            }
            uint32_t b[4][2];
#pragma unroll
            for (int ni = 0; ni < 4; ++ni) {
                int col = warp_n * 32 + ni * 8 + q;
                b[ni][0] = Bb[col * T_STRIDE + ko + c];
                b[ni][1] = Bb[col * T_STRIDE + ko + c + 4];
            }
#pragma unroll
            for (int mi = 0; mi < 4; ++mi)
#pragma unroll
                for (int ni = 0; ni < 4; ++ni) {
                    asm volatile(
                        "mma.sync.aligned.m16n8k16.row.col.f32.f16.f16.f32 "
                        "{%0,%1,%2,%3}, {%4,%5,%6,%7}, {%8,%9}, {%0,%1,%2,%3};\n"
                        : "+f"(acc[mi][ni][0]), "+f"(acc[mi][ni][1]),
                          "+f"(acc[mi][ni][2]), "+f"(acc[mi][ni][3])
                        : "r"(a[mi][0]), "r"(a[mi][1]), "r"(a[mi][2]), "r"(a[mi][3]),
                          "r"(b[ni][0]), "r"(b[ni][1]));
                }
        }
        __syncthreads();
    }

    // Epilogue: bias + relu. fp32 (final) or fp16 (inter-layer).
#pragma unroll
    for (int ni = 0; ni < 4; ++ni) {
        int col = warp_n * 32 + ni * 8 + c * 2;
        float b0 = __ldg(&bias[col]);
        float b1 = __ldg(&bias[col + 1]);
#pragma unroll
        for (int mi = 0; mi < 4; ++mi) {
            int gr0 = row0 + warp_m * 64 + mi * 16 + q;
            int gr1 = gr0 + 8;
            float v00 = fmaxf(acc[mi][ni][0] + b0, 0.f);
            float v01 = fmaxf(acc[mi][ni][1] + b1, 0.f);
            float v10 = fmaxf(acc[mi][ni][2] + b0, 0.f);
            float v11 = fmaxf(acc[mi][ni][3] + b1, 0.f);
            if (out_f32) {
                if (gr0 < NN)
                    *reinterpret_cast<float2*>(out_f32 + (size_t)gr0 * FF + col)
                        = make_float2(v00, v01);
                if (gr1 < NN)
                    *reinterpret_cast<float2*>(out_f32 + (size_t)gr1 * FF + col)
                        = make_float2(v10, v11);
            } else if (out_h_sel) {
                uint32_t* oh = reinterpret_cast<uint32_t*>(g_xh2);
                if (gr0 < NN)
                    oh[(size_t)gr0 * 64 + (col >> 1)] =
                        h2_to_u32(__floats2half2_rn(v00, v01));
                if (gr1 < NN)
                    oh[(size_t)gr1 * 64 + (col >> 1)] =
                        h2_to_u32(__floats2half2_rn(v10, v11));
            }
        }
    }
}

// ---------------------------------------------------------------------------
extern "C" void kernel_launch(void* const* d_in, const int* in_sizes, int n_in,
                              void* d_out, int out_size) {
    const float* x       = (const float*)d_in[0];   // [N, F] f32
    const int*   ei      = (const int*)d_in[1];     // [2, E] int32
    const int*   et      = (const int*)d_in[2];     // [E]    int32
    const float* weights = (const float*)d_in[3];   // [L, R, F, F]
    const float* roots   = (const float*)d_in[4];   // [L, F, F]
    const float* biases  = (const float*)d_in[5];   // [L, F]
    float* out           = (float*)d_out;           // [N, F]

    const int edge_blocks = (EE + 255) / 256;       // 6250
    const int agg_blocks  = (NB * 32 + 255) / 256;  // 50000 (warp per bin)
    const int gemm_blocks = (NN + 127) / 128;       // 782

    cudaFuncSetAttribute(gemm_kernel,
                         cudaFuncAttributeMaxDynamicSharedMemorySize, GEMM_SMEM);

    // Counting sort of edges by (relation, dst); conversions fused into place.
    hist_build_kernel<<<edge_blocks, 256>>>(ei, et);
    scan_kernel<<<NBLK, 256>>>();
    place_conv_kernel<<<edge_blocks, 256>>>(ei, et, x, weights, roots);

    // Layer 0: g_xh -> g_xh2 (fp16)
    aggregate_kernel<<<agg_blocks, 256>>>(0);
    gemm_kernel<<<gemm_blocks, 256, GEMM_SMEM>>>(0, 0, biases, nullptr, 1);

    // Layer 1: g_xh2 -> out (fp32); also re-zeros g_hist for the next replay.
    aggregate_kernel<<<agg_blocks, 256>>>(1);
    gemm_kernel<<<gemm_blocks, 256, GEMM_SMEM>>>(1, NSEG, biases + FF, out, 0);
}